// round 3
// baseline (speedup 1.0000x reference)
#include <cuda_runtime.h>
#include <math.h>

#define NB        50
#define NF_DIST   1225          // 50*49/2
#define NF_ANG    48
#define NF_DIH    47
#define NFEAT     (NF_DIST + NF_ANG + 2*NF_DIH)   // 1367

#define GROUPS    4             // frames per 256-thread block
#define GT        64            // threads per frame group

__global__ __launch_bounds__(256)
void protein_feat_kernel(const float* __restrict__ data,
                         float* __restrict__ out,
                         int n_frames)
{
    __shared__ float sx[GROUPS][GT], sy[GROUPS][GT], sz[GROUPS][GT];

    const int g     = threadIdx.x >> 6;   // frame group within block
    const int tl    = threadIdx.x & 63;   // lane within group
    const int frame = blockIdx.x * GROUPS + g;
    const bool ok   = frame < n_frames;

    // ---- load beads: thread tl owns bead tl (registers) + stage to smem ----
    float ax = 0.f, ay = 0.f, az = 0.f;
    if (ok && tl < NB) {
        const float* p = data + (size_t)frame * NB * 3 + 3 * tl;
        ax = p[0]; ay = p[1]; az = p[2];
        sx[g][tl] = ax; sy[g][tl] = ay; sz[g][tl] = az;
    }
    __syncthreads();

    if (!ok) return;

    float* o = out + (size_t)frame * NFEAT;

    // ---- distances: row loop over pair separation inc ----
    // lane tl computes pair (tl, tl+inc); bead A is register-resident.
    // warp0 (tl<32): rows inc=1..49. warp1 (tl>=32): active only while
    // 50-inc > 32, i.e. inc <= 17 -- uniform early exit per warp.
    {
        const int last_inc = (tl < 32) ? (NB - 1) : (NB - 1 - 32);
        int rowoff = 0;
        for (int inc = 1; inc <= last_inc; ++inc) {
            const int n = NB - inc;
            if (tl < n) {
                const int j = tl + inc;
                const float dx = sx[g][j] - ax;
                const float dy = sy[g][j] - ay;
                const float dz = sz[g][j] - az;
                const float s  = fmaf(dx, dx, fmaf(dy, dy, dz * dz));
                o[rowoff + tl] = s * rsqrtf(s);
            }
            rowoff += n;
        }
    }

    // ---- angles + dihedrals: 142 features, f-linear over the 64 lanes ----
    for (int k = tl; k < NF_ANG + 2 * NF_DIH; k += GT) {
        float res;

        if (k < NF_ANG) {
            const int a = k;
            const float b1x = sx[g][a]     - sx[g][a + 1];
            const float b1y = sy[g][a]     - sy[g][a + 1];
            const float b1z = sz[g][a]     - sz[g][a + 1];
            const float b2x = sx[g][a + 2] - sx[g][a + 1];
            const float b2y = sy[g][a + 2] - sy[g][a + 1];
            const float b2z = sz[g][a + 2] - sz[g][a + 1];

            const float dot = fmaf(b1x, b2x, fmaf(b1y, b2y, b1z * b2z));
            const float n1  = fmaf(b1x, b1x, fmaf(b1y, b1y, b1z * b1z));
            const float n2  = fmaf(b2x, b2x, fmaf(b2y, b2y, b2z * b2z));
            float ct = dot * rsqrtf(n1 * n2);
            ct = fminf(1.0f, fmaxf(-1.0f, ct));
            res = acosf(ct);
        } else {
            int d = k - NF_ANG;
            const bool want_sin = d >= NF_DIH;
            if (want_sin) d -= NF_DIH;

            const float axv = sx[g][d + 1] - sx[g][d];
            const float ayv = sy[g][d + 1] - sy[g][d];
            const float azv = sz[g][d + 1] - sz[g][d];
            const float bx  = sx[g][d + 2] - sx[g][d + 1];
            const float by  = sy[g][d + 2] - sy[g][d + 1];
            const float bz  = sz[g][d + 2] - sz[g][d + 1];
            const float cx  = sx[g][d + 3] - sx[g][d + 2];
            const float cy  = sy[g][d + 3] - sy[g][d + 2];
            const float cz  = sz[g][d + 3] - sz[g][d + 2];

            const float p1x = ayv * bz - azv * by;
            const float p1y = azv * bx - axv * bz;
            const float p1z = axv * by - ayv * bx;
            const float p2x = by * cz - bz * cy;
            const float p2y = bz * cx - bx * cz;
            const float p2z = bx * cy - by * cx;

            const float n1sq = fmaf(p1x, p1x, fmaf(p1y, p1y, p1z * p1z));
            const float n2sq = fmaf(p2x, p2x, fmaf(p2y, p2y, p2z * p2z));
            const float inv12 = rsqrtf(n1sq * n2sq);

            if (!want_sin) {
                const float dp = fmaf(p1x, p2x, fmaf(p1y, p2y, p1z * p2z));
                res = dp * inv12;
            } else {
                const float qx = p1y * p2z - p1z * p2y;
                const float qy = p1z * p2x - p1x * p2z;
                const float qz = p1x * p2y - p1y * p2x;
                const float num  = fmaf(qx, bx, fmaf(qy, by, qz * bz));
                const float bnsq = fmaf(bx, bx, fmaf(by, by, bz * bz));
                res = num * inv12 * rsqrtf(bnsq);
            }
        }

        o[NF_DIST + k] = res;
    }
}

extern "C" void kernel_launch(void* const* d_in, const int* in_sizes, int n_in,
                              void* d_out, int out_size)
{
    const float* data = (const float*)d_in[0];
    float* out = (float*)d_out;
    const int n_frames = in_sizes[0] / (NB * 3);
    const int n_blocks = (n_frames + GROUPS - 1) / GROUPS;

    protein_feat_kernel<<<n_blocks, GROUPS * GT>>>(data, out, n_frames);
}

// round 4
// speedup vs baseline: 1.1607x; 1.1607x over previous
#include <cuda_runtime.h>
#include <stdint.h>
#include <math.h>

#define NB        50
#define NF_DIST   1225          // 50*49/2
#define NF_ANG    48
#define NF_DIH    47
#define NFEAT     (NF_DIST + NF_ANG + 2*NF_DIH)   // 1367

#define OFF_ANG   NF_DIST                 // 1225
#define OFF_DCOS  (NF_DIST + NF_ANG)      // 1273
#define OFF_DSIN  (OFF_DCOS + NF_DIH)     // 1320

// Compile-time pair table: i | (j << 6), cgnet order (by separation, then i).
struct PairTable { uint16_t v[NF_DIST]; };
constexpr PairTable make_pair_table() {
    PairTable t{};
    int f = 0;
    for (int inc = 1; inc < NB; ++inc)
        for (int i = 0; i < NB - inc; ++i)
            t.v[f++] = (uint16_t)(i | ((i + inc) << 6));
    return t;
}
__device__ constexpr PairTable g_pairs = make_pair_table();

__global__ __launch_bounds__(256)
void protein_feat_kernel(const float* __restrict__ data,
                         float* __restrict__ out)
{
    // Flat bead coords: x[i]=sraw[3i], y[i]=sraw[3i+1], z[i]=sraw[3i+2].
    // Stride-3 LDS across consecutive i is bank-conflict-free (gcd(3,32)=1).
    __shared__ float sraw[NB * 3];

    const int frame = blockIdx.x;
    const int tid   = threadIdx.x;

    const float* p = data + (size_t)frame * NB * 3;
    if (tid < NB * 3) sraw[tid] = p[tid];   // fully coalesced stage
    __syncthreads();

    float* o = out + (size_t)frame * NFEAT;

    // ------------------- distances (features 0..1224) -------------------
    // 1225 = 4*256 + 201 : four full unrolled passes + a partial one.
    #pragma unroll
    for (int it = 0; it < 4; ++it) {
        const int f = tid + it * 256;
        const unsigned t = g_pairs.v[f];
        const int i3 = (t & 63) * 3;
        const int j3 = (t >> 6) * 3;
        const float dx = sraw[j3 + 0] - sraw[i3 + 0];
        const float dy = sraw[j3 + 1] - sraw[i3 + 1];
        const float dz = sraw[j3 + 2] - sraw[i3 + 2];
        const float s  = fmaf(dx, dx, fmaf(dy, dy, dz * dz));
        o[f] = s * rsqrtf(s);
    }
    if (tid < NF_DIST - 1024) {
        const int f = 1024 + tid;
        const unsigned t = g_pairs.v[f];
        const int i3 = (t & 63) * 3;
        const int j3 = (t >> 6) * 3;
        const float dx = sraw[j3 + 0] - sraw[i3 + 0];
        const float dy = sraw[j3 + 1] - sraw[i3 + 1];
        const float dz = sraw[j3 + 2] - sraw[i3 + 2];
        const float s  = fmaf(dx, dx, fmaf(dy, dy, dz * dz));
        o[f] = s * rsqrtf(s);
    }

    // ------------------- angles: warps 0-1 (tid 0..47) -------------------
    if (tid < NF_ANG) {
        const int a3 = tid * 3;
        const float b1x = sraw[a3 + 0] - sraw[a3 + 3];
        const float b1y = sraw[a3 + 1] - sraw[a3 + 4];
        const float b1z = sraw[a3 + 2] - sraw[a3 + 5];
        const float b2x = sraw[a3 + 6] - sraw[a3 + 3];
        const float b2y = sraw[a3 + 7] - sraw[a3 + 4];
        const float b2z = sraw[a3 + 8] - sraw[a3 + 5];

        const float dot = fmaf(b1x, b2x, fmaf(b1y, b2y, b1z * b2z));
        const float n1  = fmaf(b1x, b1x, fmaf(b1y, b1y, b1z * b1z));
        const float n2  = fmaf(b2x, b2x, fmaf(b2y, b2y, b2z * b2z));
        float ct = dot * rsqrtf(n1 * n2);
        ct = fminf(1.0f, fmaxf(-1.0f, ct));
        o[OFF_ANG + tid] = acosf(ct);
    }

    // ---------- dihedrals (cos+sin fused): warp 2 (tid 64..110) ----------
    if (tid >= 64 && tid < 64 + NF_DIH) {
        const int d  = tid - 64;
        const int d3 = d * 3;

        const float ax = sraw[d3 + 3] - sraw[d3 + 0];
        const float ay = sraw[d3 + 4] - sraw[d3 + 1];
        const float az = sraw[d3 + 5] - sraw[d3 + 2];
        const float bx = sraw[d3 + 6] - sraw[d3 + 3];
        const float by = sraw[d3 + 7] - sraw[d3 + 4];
        const float bz = sraw[d3 + 8] - sraw[d3 + 5];
        const float cx = sraw[d3 + 9] - sraw[d3 + 6];
        const float cy = sraw[d3 +10] - sraw[d3 + 7];
        const float cz = sraw[d3 +11] - sraw[d3 + 8];

        // p1 = a x b, p2 = b x c
        const float p1x = ay * bz - az * by;
        const float p1y = az * bx - ax * bz;
        const float p1z = ax * by - ay * bx;
        const float p2x = by * cz - bz * cy;
        const float p2y = bz * cx - bx * cz;
        const float p2z = bx * cy - by * cx;

        const float n1sq  = fmaf(p1x, p1x, fmaf(p1y, p1y, p1z * p1z));
        const float n2sq  = fmaf(p2x, p2x, fmaf(p2y, p2y, p2z * p2z));
        const float inv12 = rsqrtf(n1sq * n2sq);

        // cos
        const float dp = fmaf(p1x, p2x, fmaf(p1y, p2y, p1z * p2z));
        o[OFF_DCOS + d] = dp * inv12;

        // sin: cross(p1, p2) . b / (|p1||p2||b|)
        const float qx = p1y * p2z - p1z * p2y;
        const float qy = p1z * p2x - p1x * p2z;
        const float qz = p1x * p2y - p1y * p2x;
        const float num  = fmaf(qx, bx, fmaf(qy, by, qz * bz));
        const float bnsq = fmaf(bx, bx, fmaf(by, by, bz * bz));
        o[OFF_DSIN + d] = num * inv12 * rsqrtf(bnsq);
    }
}

extern "C" void kernel_launch(void* const* d_in, const int* in_sizes, int n_in,
                              void* d_out, int out_size)
{
    const float* data = (const float*)d_in[0];
    float* out = (float*)d_out;
    const int n_frames = in_sizes[0] / (NB * 3);

    protein_feat_kernel<<<n_frames, 256>>>(data, out);
}

// round 5
// speedup vs baseline: 1.2222x; 1.0530x over previous
#include <cuda_runtime.h>
#include <stdint.h>
#include <math.h>

#define NB        50
#define NF_DIST   1225          // 50*49/2
#define NF_ANG    48
#define NF_DIH    47
#define NFEAT     (NF_DIST + NF_ANG + 2*NF_DIH)   // 1367

#define OFF_ANG   NF_DIST                 // 1225
#define OFF_DCOS  (NF_DIST + NF_ANG)      // 1273
#define OFF_DSIN  (OFF_DCOS + NF_DIH)     // 1320

#define NTASK     175           // sum over g=0..6 of (50 - (8g+1))
#define T_ANG0    NTASK         // 175
#define T_DIH0    (NTASK + NF_ANG)   // 223
#define NTHREADS  288           // 175 dist + 48 ang + 47 dih (+18 idle)

// ---------------------------------------------------------------------------
// Compile-time task table: thread owns bead i, sweeps rows inc0..inc0+7.
// Packed: i (bits 0-5) | inc0 (bits 6-11) | f0=row base offset (bits 12+).
// Row base of inc: C(inc-1) = (inc-1)(100-inc)/2.
// ---------------------------------------------------------------------------
struct TaskTable { uint32_t v[NTASK]; };
constexpr TaskTable make_tasks() {
    TaskTable t{};
    int n = 0;
    for (int g = 0; g < 7; ++g) {
        const int inc0 = 8 * g + 1;
        const int len0 = NB - inc0;
        const int f0   = (inc0 - 1) * (100 - inc0) / 2;
        for (int i = 0; i < len0; ++i)
            t.v[n++] = (uint32_t)(i | (inc0 << 6) | (f0 << 12));
    }
    return t;
}
__device__ constexpr TaskTable g_tasks = make_tasks();

__global__ __launch_bounds__(NTHREADS)
void protein_feat_kernel(const float* __restrict__ data,
                         float* __restrict__ out)
{
    // Flat coords: x[i]=sraw[3i], y=3i+1, z=3i+2. Stride-3 is conflict-free.
    __shared__ float sraw[NB * 3];

    const int frame = blockIdx.x;
    const int tid   = threadIdx.x;

    const float* p = data + (size_t)frame * NB * 3;
    if (tid < NB * 3) sraw[tid] = p[tid];
    __syncthreads();

    float* o = out + (size_t)frame * NFEAT;

    if (tid < NTASK) {
        // ---- distances: bead i vs beads i+inc0 .. i+inc0+7 ----
        const uint32_t tv  = g_tasks.v[tid];
        const int i        = tv & 63;
        const int inc0     = (tv >> 6) & 63;
        const int rowlen   = NB - inc0;
        int f              = (int)(tv >> 12) + i;
        int j              = i + inc0;

        const int i3 = 3 * i;
        const float ax = sraw[i3 + 0];
        const float ay = sraw[i3 + 1];
        const float az = sraw[i3 + 2];

        #pragma unroll
        for (int k = 0; k < 8; ++k) {
            if (j < NB) {
                const int j3 = 3 * j;
                const float dx = sraw[j3 + 0] - ax;
                const float dy = sraw[j3 + 1] - ay;
                const float dz = sraw[j3 + 2] - az;
                const float s  = fmaf(dx, dx, fmaf(dy, dy, dz * dz));
                o[f] = s * rsqrtf(s);
            }
            f += rowlen - k;   // next row is one shorter
            ++j;
        }
    }
    else if (tid < T_DIH0) {
        // ---- angles: tid 175..222 -> a = 0..47 ----
        const int a3 = (tid - T_ANG0) * 3;
        const float b1x = sraw[a3 + 0] - sraw[a3 + 3];
        const float b1y = sraw[a3 + 1] - sraw[a3 + 4];
        const float b1z = sraw[a3 + 2] - sraw[a3 + 5];
        const float b2x = sraw[a3 + 6] - sraw[a3 + 3];
        const float b2y = sraw[a3 + 7] - sraw[a3 + 4];
        const float b2z = sraw[a3 + 8] - sraw[a3 + 5];

        const float dot = fmaf(b1x, b2x, fmaf(b1y, b2y, b1z * b2z));
        const float n1  = fmaf(b1x, b1x, fmaf(b1y, b1y, b1z * b1z));
        const float n2  = fmaf(b2x, b2x, fmaf(b2y, b2y, b2z * b2z));
        float ct = dot * rsqrtf(n1 * n2);
        ct = fminf(1.0f, fmaxf(-1.0f, ct));
        o[OFF_ANG + (tid - T_ANG0)] = acosf(ct);
    }
    else if (tid < T_DIH0 + NF_DIH) {
        // ---- dihedrals (cos+sin fused): tid 223..269 -> d = 0..46 ----
        const int d  = tid - T_DIH0;
        const int d3 = d * 3;

        const float ax = sraw[d3 + 3] - sraw[d3 + 0];
        const float ay = sraw[d3 + 4] - sraw[d3 + 1];
        const float az = sraw[d3 + 5] - sraw[d3 + 2];
        const float bx = sraw[d3 + 6] - sraw[d3 + 3];
        const float by = sraw[d3 + 7] - sraw[d3 + 4];
        const float bz = sraw[d3 + 8] - sraw[d3 + 5];
        const float cx = sraw[d3 + 9] - sraw[d3 + 6];
        const float cy = sraw[d3 +10] - sraw[d3 + 7];
        const float cz = sraw[d3 +11] - sraw[d3 + 8];

        const float p1x = ay * bz - az * by;
        const float p1y = az * bx - ax * bz;
        const float p1z = ax * by - ay * bx;
        const float p2x = by * cz - bz * cy;
        const float p2y = bz * cx - bx * cz;
        const float p2z = bx * cy - by * cx;

        const float n1sq  = fmaf(p1x, p1x, fmaf(p1y, p1y, p1z * p1z));
        const float n2sq  = fmaf(p2x, p2x, fmaf(p2y, p2y, p2z * p2z));
        const float inv12 = rsqrtf(n1sq * n2sq);

        const float dp = fmaf(p1x, p2x, fmaf(p1y, p2y, p1z * p2z));
        o[OFF_DCOS + d] = dp * inv12;

        const float qx = p1y * p2z - p1z * p2y;
        const float qy = p1z * p2x - p1x * p2z;
        const float qz = p1x * p2y - p1y * p2x;
        const float num  = fmaf(qx, bx, fmaf(qy, by, qz * bz));
        const float bnsq = fmaf(bx, bx, fmaf(by, by, bz * bz));
        o[OFF_DSIN + d] = num * inv12 * rsqrtf(bnsq);
    }
}

extern "C" void kernel_launch(void* const* d_in, const int* in_sizes, int n_in,
                              void* d_out, int out_size)
{
    const float* data = (const float*)d_in[0];
    float* out = (float*)d_out;
    const int n_frames = in_sizes[0] / (NB * 3);

    protein_feat_kernel<<<n_frames, NTHREADS>>>(data, out);
}